// round 16
// baseline (speedup 1.0000x reference)
#include <cuda_runtime.h>
#include <cuda_bf16.h>
#include <cstdint>

#define NRES  2048
#define TOPK  32
#define EIN   416
#define NSTG  7            // 7 stages of 64 K-cols (448 padded)
#define EFEAT 128
#define NROWS 8192
#define NEDGE 262144

#define ATERM 16384        // bytes per A/B term (fragment-order, no padding)
#define ESTRIDE 129        // fp32 epilogue stride

// ---------------- device scratch ----------------
__device__ float g_atoms[NROWS * 15];
__device__ float g_ca3[NROWS * 3];
__device__ float g_dn[NEDGE];
__device__ int   g_eidx[NEDGE];
__device__ __nv_bfloat16 g_Bhi[NSTG * 8192];   // [stage][n][64] bf16
__device__ __nv_bfloat16 g_Blo[NSTG * 8192];

__constant__ int c_pa[24] = {0,2,3,4,1,1,1,1,0,0,0,4,4,3,0,2,3,4,2,3,4,2,3,2};
__constant__ int c_pb[24] = {0,2,3,4,0,2,3,4,2,3,4,2,3,2,1,1,1,1,0,0,0,4,4,3};
__constant__ float c_freq[8] = {
    1.0f, 0.31622776601683794f, 0.1f, 0.031622776601683794f,
    0.01f, 0.0031622776601683794f, 0.001f, 0.00031622776601683794f};

__device__ __forceinline__ void mma16816(float* c, const uint32_t* a, uint32_t b0, uint32_t b1) {
    asm volatile("mma.sync.aligned.m16n8k16.row.col.f32.bf16.bf16.f32 "
                 "{%0,%1,%2,%3}, {%4,%5,%6,%7}, {%8,%9}, {%0,%1,%2,%3};"
                 : "+f"(c[0]), "+f"(c[1]), "+f"(c[2]), "+f"(c[3])
                 : "r"(a[0]), "r"(a[1]), "r"(a[2]), "r"(a[3]), "r"(b0), "r"(b1));
}

// ---------------- K1: per-residue atoms ----------------
__global__ void atoms_kernel(const float* __restrict__ X) {
    int r = blockIdx.x * blockDim.x + threadIdx.x;
    if (r >= NROWS) return;
    const float* x = X + (size_t)r * 12;
    float Nx = x[0], Ny = x[1], Nz = x[2];
    float Ax = x[3], Ay = x[4], Az = x[5];
    float Cx = x[6], Cy = x[7], Cz = x[8];
    float Ox = x[9], Oy = x[10], Oz = x[11];
    float bx = Ax - Nx, by = Ay - Ny, bz = Az - Nz;
    float cx = Cx - Ax, cy = Cy - Ay, cz = Cz - Az;
    float ax = by * cz - bz * cy;
    float ay = bz * cx - bx * cz;
    float az = bx * cy - by * cx;
    float Bx = -0.58273431f * ax + 0.56802827f * bx - 0.54067466f * cx + Ax;
    float By = -0.58273431f * ay + 0.56802827f * by - 0.54067466f * cy + Ay;
    float Bz = -0.58273431f * az + 0.56802827f * bz - 0.54067466f * cz + Az;
    float* o = g_atoms + (size_t)r * 15;
    o[0] = Nx; o[1] = Ny; o[2] = Nz;
    o[3] = Ax; o[4] = Ay; o[5] = Az;
    o[6] = Cx; o[7] = Cy; o[8] = Cz;
    o[9] = Ox; o[10] = Oy; o[11] = Oz;
    o[12] = Bx; o[13] = By; o[14] = Bz;
    g_ca3[(size_t)r * 3 + 0] = Ax;
    g_ca3[(size_t)r * 3 + 1] = Ay;
    g_ca3[(size_t)r * 3 + 2] = Az;
}

// ---------------- K2: W -> bf16 hi/lo stage images, [stage][n][64] ----------------
__global__ void prepw_kernel(const float* __restrict__ W) {
    int idx = blockIdx.x * blockDim.x + threadIdx.x;
    if (idx >= NSTG * 8192) return;
    int s = idx >> 13;
    int rem = idx & 8191;
    int n = rem >> 6;
    int c = rem & 63;
    int k = s * 64 + c;
    float v = (k < EIN) ? W[(size_t)k * EFEAT + n] : 0.0f;
    __nv_bfloat16 h = __float2bfloat16(v);
    float lo = v - __bfloat162float(h);
    g_Bhi[idx] = h;
    g_Blo[idx] = __float2bfloat16(lo);
}

// ---------------- K3: warp-per-row top-32, tournament + segment rescan ----------------
__global__ void __launch_bounds__(256) topk_kernel(const float* __restrict__ mask,
                                                   float* __restrict__ outIdxF,
                                                   int writeIdx) {
    extern __shared__ float dynT[];
    float* sD = dynT;                 // 8 * 2048
    float* sCa = dynT + 8 * NRES;     // 2048 * 3
    float* sM = dynT + 11 * NRES;     // 2048

    int tid = threadIdx.x;
    int warp = tid >> 5, lane = tid & 31;
    int row = blockIdx.x * 8 + warp;
    int bq = row >> 11, i = row & (NRES - 1);
    float* D = sD + warp * NRES;

    for (int t = tid; t < NRES * 3; t += 256)
        sCa[t] = g_ca3[(size_t)bq * NRES * 3 + t];
    for (int t = tid; t < NRES; t += 256)
        sM[t] = mask[(size_t)bq * NRES + t];
    __syncthreads();

    float cax = sCa[i * 3 + 0];
    float cay = sCa[i * 3 + 1];
    float caz = sCa[i * 3 + 2];
    float mi = sM[i];

    float lmax = 0.0f;
    #pragma unroll 4
    for (int s = 0; s < NRES / 32; s++) {
        int j = lane + 32 * s;
        float dx = sCa[j * 3 + 0] - cax;
        float dy = sCa[j * 3 + 1] - cay;
        float dz = sCa[j * 3 + 2] - caz;
        float d = sqrtf(dx * dx + dy * dy + dz * dz + 1e-6f);
        float dm = mi * sM[j] * d;
        D[j] = dm;
        lmax = fmaxf(lmax, dm);
    }
    #pragma unroll
    for (int off = 16; off; off >>= 1)
        lmax = fmaxf(lmax, __shfl_xor_sync(0xffffffffu, lmax, off));
    __syncwarp();
    #pragma unroll 4
    for (int s = 0; s < NRES / 32; s++) {
        int j = lane + 32 * s;
        float m2 = mi * sM[j];
        D[j] += (1.0f - m2) * lmax;
    }
    __syncwarp();

    const float INF = __int_as_float(0x7f800000);

    // per-lane segment min: lane l owns D[64l .. 64l+63]
    float bv = INF;
    int bidx = 0x7fffffff;
    #pragma unroll 8
    for (int t = 0; t < 64; t++) {
        int idx = (lane << 6) + ((t + lane) & 63);   // rotated: conflict-free
        float v = D[idx];
        if (v < bv || (v == bv && idx < bidx)) { bv = v; bidx = idx; }
    }

    for (int sel = 0; sel < TOPK; sel++) {
        float v = bv;
        int ix = bidx;
        #pragma unroll
        for (int off = 16; off; off >>= 1) {
            float vv = __shfl_xor_sync(0xffffffffu, v, off);
            int   ii = __shfl_xor_sync(0xffffffffu, ix, off);
            if (vv < v || (vv == v && ii < ix)) { v = vv; ix = ii; }
        }
        if (lane == 0) {
            g_eidx[(size_t)row * TOPK + sel] = ix;
            g_dn[(size_t)row * TOPK + sel] = v;
            if (writeIdx) outIdxF[(size_t)row * TOPK + sel] = (float)ix;
            D[ix] = INF;
        }
        __syncwarp();
        int o = ix >> 6;
        int i2 = (o << 6) + 2 * lane;
        float2 pr = *(const float2*)&D[i2];
        float rv; int ridx;
        if (pr.x <= pr.y) { rv = pr.x; ridx = i2; }
        else { rv = pr.y; ridx = i2 + 1; }
        #pragma unroll
        for (int off = 16; off; off >>= 1) {
            float vv = __shfl_xor_sync(0xffffffffu, rv, off);
            int   ii = __shfl_xor_sync(0xffffffffu, ridx, off);
            if (vv < rv || (vv == rv && ii < ridx)) { rv = vv; ridx = ii; }
        }
        if (lane == o) { bv = rv; bidx = ridx; }
        __syncwarp();
    }
}

// ---------------- K4: mma.sync bf16-split GEMM + LN, fragment-order smem ----------------
// A tiles: [rt 0..7][ks 0..3] of 512 B; within tile addr = lane*16 + reg*4.
//   (row rl 0..15, koff 0..15): lane = (rl&7)*4 + (koff&7)/2, reg = 2*(koff>=8) + (rl>=8)
// B tiles: [nt 0..15][ks 0..3] of 256 B; within tile addr = lane*8 + reg*4.
//   (col cl 0..7, koff): lane = cl*4 + (koff&7)/2, reg = (koff>=8)
__global__ void __launch_bounds__(256, 2) gemm_mma_kernel(const float* __restrict__ gamma,
                                                          const float* __restrict__ beta,
                                                          float* __restrict__ out) {
    extern __shared__ char dyn[];
    __shared__ float sPos[128][16];
    __shared__ float sDist[128][25];
    __shared__ float sGam[128], sBet[128];
    __shared__ float sMu[128], sInv[128];

    char* Ah = dyn;                    // fragment-order, 16 KB
    char* Al = dyn + ATERM;
    char* Bh = dyn + 2 * ATERM;
    char* Bl = dyn + 3 * ATERM;
    float* E = (float*)dyn;            // epilogue reuse: 128 x ESTRIDE fp32 (66048 B)

    int tile = blockIdx.x;
    int tid = threadIdx.x;
    int wid = tid >> 5, lane = tid & 31;
    int wm = wid >> 1, wn = wid & 1;

    // preamble
    if (tid < 128) {
        sGam[tid] = gamma[tid];
        sBet[tid] = beta[tid];
        int m = tid;
        int res = tile * 4 + (m >> 5);
        int e = m & 31;
        int bq = res >> 11;
        int i = res & (NRES - 1);
        int j = g_eidx[(size_t)res * TOPK + e];
        sDist[m][0] = g_dn[(size_t)res * TOPK + e];
        const float* AI = g_atoms + (size_t)res * 15;
        const float* AJ = g_atoms + (size_t)(bq * NRES + j) * 15;
        float ai[15], aj[15];
        #pragma unroll
        for (int t = 0; t < 15; t++) { ai[t] = AI[t]; aj[t] = AJ[t]; }
        #pragma unroll
        for (int p = 0; p < 24; p++) {
            int a3 = c_pa[p] * 3, b3 = c_pb[p] * 3;
            float dx = ai[a3 + 0] - aj[b3 + 0];
            float dy = ai[a3 + 1] - aj[b3 + 1];
            float dz = ai[a3 + 2] - aj[b3 + 2];
            sDist[m][1 + p] = sqrtf(dx * dx + dy * dy + dz * dz + 1e-6f);
        }
        float d = (float)(j - i);
        #pragma unroll
        for (int k = 0; k < 8; k++) {
            float s, c;
            sincosf(d * c_freq[k], &s, &c);
            sPos[m][k] = c;
            sPos[m][8 + k] = s;
        }
    }

    float acc[2][8][4];
    #pragma unroll
    for (int mi = 0; mi < 2; mi++)
        #pragma unroll
        for (int ni = 0; ni < 8; ni++)
            #pragma unroll
            for (int q = 0; q < 4; q++) acc[mi][ni][q] = 0.0f;

    for (int s = 0; s < NSTG; s++) {
        __syncthreads();   // prior compute done (and preamble on s=0)

        // ---- A fill: features, bf16 hi/lo, written in fragment order ----
        for (int t = tid; t < 1024; t += 256) {
            int m = t >> 3;
            int g = t & 7;             // 8-col group; ks = g>>1, khalf = g&1
            int k0 = s * 64 + g * 8;
            float v[8];
            if (k0 < 16) {
                #pragma unroll
                for (int q = 0; q < 8; q++) v[q] = sPos[m][k0 + q];
            } else if (k0 >= EIN) {
                #pragma unroll
                for (int q = 0; q < 8; q++) v[q] = 0.0f;
            } else {
                float Dv = (k0 < 32) ? sDist[m][0] : sDist[m][1 + ((k0 - 32) >> 4)];
                #pragma unroll
                for (int q = 0; q < 8; q++) {
                    int mth = (k0 + q) & 15;
                    float tt = (Dv - (2.0f + 1.3333333333f * (float)mth)) * 0.8f;
                    v[q] = __expf(-tt * tt);
                }
            }
            uint32_t hp[4], lp[4];
            #pragma unroll
            for (int q = 0; q < 4; q++) {
                float v0 = v[2 * q], v1 = v[2 * q + 1];
                __nv_bfloat16 h0 = __float2bfloat16(v0);
                __nv_bfloat16 h1 = __float2bfloat16(v1);
                __nv_bfloat162 h2; h2.x = h0; h2.y = h1;
                __nv_bfloat162 l2 = __floats2bfloat162_rn(v0 - __bfloat162float(h0),
                                                          v1 - __bfloat162float(h1));
                hp[q] = *(uint32_t*)&h2;
                lp[q] = *(uint32_t*)&l2;
            }
            // fragment-order dest: tile (m>>4)*4 + (g>>1); lane (m&7)*4+q; reg 2*(g&1)+((m>>3)&1)
            int tb = ((m >> 4) * 4 + (g >> 1)) * 512 + (m & 7) * 64 + (2 * (g & 1) + ((m >> 3) & 1)) * 4;
            #pragma unroll
            for (int q = 0; q < 4; q++) {
                *(uint32_t*)(Ah + tb + q * 16) = hp[q];
                *(uint32_t*)(Al + tb + q * 16) = lp[q];
            }
        }
        // ---- B fill: stage image -> fragment order ----
        {
            const uint32_t* srcH = (const uint32_t*)(g_Bhi + s * 8192);
            const uint32_t* srcL = (const uint32_t*)(g_Blo + s * 8192);
            for (int t = tid; t < 4096; t += 256) {
                int n = t >> 5, kp = t & 31;   // kp = k-pair within 64-col stage
                int off = ((n >> 3) * 4 + (kp >> 3)) * 256
                        + ((n & 7) * 4 + (kp & 3)) * 8 + ((kp >> 2) & 1) * 4;
                *(uint32_t*)(Bh + off) = srcH[t];
                *(uint32_t*)(Bl + off) = srcL[t];
            }
        }
        __syncthreads();

        // ---- compute: 4 k16-steps, vector fragment loads ----
        #pragma unroll
        for (int ks = 0; ks < 4; ks++) {
            uint32_t ahi[2][4], alo[2][4];
            #pragma unroll
            for (int mi = 0; mi < 2; mi++) {
                const char* ar = Ah + ((wm * 2 + mi) * 4 + ks) * 512 + lane * 16;
                uint4 h = *(const uint4*)ar;
                uint4 l = *(const uint4*)(ar + ATERM);
                ahi[mi][0] = h.x; ahi[mi][1] = h.y; ahi[mi][2] = h.z; ahi[mi][3] = h.w;
                alo[mi][0] = l.x; alo[mi][1] = l.y; alo[mi][2] = l.z; alo[mi][3] = l.w;
            }
            #pragma unroll
            for (int ni = 0; ni < 8; ni++) {
                const char* br = Bh + ((wn * 8 + ni) * 4 + ks) * 256 + lane * 8;
                uint2 bh = *(const uint2*)br;
                uint2 bl = *(const uint2*)(br + ATERM);
                #pragma unroll
                for (int mi = 0; mi < 2; mi++) {
                    mma16816(acc[mi][ni], ahi[mi], bh.x, bh.y);
                    mma16816(acc[mi][ni], ahi[mi], bl.x, bl.y);
                    mma16816(acc[mi][ni], alo[mi], bh.x, bh.y);
                }
            }
        }
    }

    // ---- epilogue ----
    __syncthreads();
    #pragma unroll
    for (int mi = 0; mi < 2; mi++) {
        int r0 = wm * 32 + mi * 16 + (lane >> 2);
        #pragma unroll
        for (int ni = 0; ni < 8; ni++) {
            int c0 = wn * 64 + ni * 8 + (lane & 3) * 2;
            E[r0 * ESTRIDE + c0] = acc[mi][ni][0];
            E[r0 * ESTRIDE + c0 + 1] = acc[mi][ni][1];
            E[(r0 + 8) * ESTRIDE + c0] = acc[mi][ni][2];
            E[(r0 + 8) * ESTRIDE + c0 + 1] = acc[mi][ni][3];
        }
    }
    __syncthreads();

    if (tid < 128) {
        int r = tid;
        float sum = 0.0f, sq = 0.0f;
        #pragma unroll 16
        for (int c = 0; c < 128; c++) {
            float v = E[r * ESTRIDE + c];
            sum += v;
            sq += v * v;
        }
        float mu = sum * (1.0f / 128.0f);
        float var = sq * (1.0f / 128.0f) - mu * mu;
        sMu[r] = mu;
        sInv[r] = rsqrtf(fmaxf(var, 0.0f) + 1e-5f);
    }
    __syncthreads();

    for (int t = tid; t < 128 * 32; t += 256) {
        int m = t >> 5, q = t & 31;
        float mu = sMu[m], inv = sInv[m];
        float o0 = (E[m * ESTRIDE + q * 4 + 0] - mu) * inv * sGam[q * 4 + 0] + sBet[q * 4 + 0];
        float o1 = (E[m * ESTRIDE + q * 4 + 1] - mu) * inv * sGam[q * 4 + 1] + sBet[q * 4 + 1];
        float o2 = (E[m * ESTRIDE + q * 4 + 2] - mu) * inv * sGam[q * 4 + 2] + sBet[q * 4 + 2];
        float o3 = (E[m * ESTRIDE + q * 4 + 3] - mu) * inv * sGam[q * 4 + 3] + sBet[q * 4 + 3];
        float4 o = make_float4(o0, o1, o2, o3);
        *(float4*)(out + ((size_t)tile * 128 + m) * EFEAT + q * 4) = o;
    }
}

// ---------------- launch ----------------
extern "C" void kernel_launch(void* const* d_in, const int* in_sizes, int n_in,
                              void* d_out, int out_size) {
    const float* X = (const float*)d_in[0];
    const float* mask = (const float*)d_in[1];
    const float* W = (const float*)d_in[2];
    const float* gamma = (const float*)d_in[3];
    const float* beta = (const float*)d_in[4];
    float* out = (float*)d_out;

    const int E_ELEMS = NEDGE * EFEAT;
    int writeIdx = (out_size >= E_ELEMS + NEDGE) ? 1 : 0;
    float* outIdx = out + E_ELEMS;

    const int DYN = 66048;          // max(4*ATERM=65536, epilogue 128*129*4=66048)
    const int TOPK_DYN = 98304;     // 12 * 2048 * 4
    cudaFuncSetAttribute(topk_kernel, cudaFuncAttributeMaxDynamicSharedMemorySize, TOPK_DYN);
    cudaFuncSetAttribute(gemm_mma_kernel, cudaFuncAttributeMaxDynamicSharedMemorySize, DYN);

    atoms_kernel<<<(NROWS + 255) / 256, 256>>>(X);
    prepw_kernel<<<(NSTG * 8192 + 255) / 256, 256>>>(W);
    topk_kernel<<<NROWS / 8, 256, TOPK_DYN>>>(mask, outIdx, writeIdx);
    gemm_mma_kernel<<<NEDGE / 128, 256, DYN>>>(gamma, beta, out);
}